// round 4
// baseline (speedup 1.0000x reference)
#include <cuda_runtime.h>

// out[(b*N+n)*D + c, s] = q[b, s, c] * w[n, c]
// q: (B=8, S=2048, D=256) fp32, c contiguous
// w: (N=20, D=256) fp32
// out: (B*N=160, D=256, S=2048) fp32, s contiguous
//
// Write-bound (335.5 MB out vs 16.8 MB in). Shared-memory 32x32 tile
// transpose; each tile written 20x (one coalesced STG.128 stream per class).

#define BB 8
#define SS 2048
#define DD 256
#define NN 20

__global__ __launch_bounds__(256)
void FeatureReweightingModule_72447508349057_kernel(
    const float* __restrict__ q,
    const float* __restrict__ w,
    float* __restrict__ out)
{
    __shared__ float tile[32][33];     // [s_local][c_local], padded
    __shared__ float ws[NN][32];       // w slice for this c-tile

    const int s0 = blockIdx.x << 5;    // s tile origin (64 tiles)
    const int c0 = blockIdx.y << 5;    // c tile origin (8 tiles)
    const int b  = blockIdx.z;         // batch (8)

    const int tid = threadIdx.x;       // 256 threads

    // Stage the 20x32 weight slice for this channel tile.
    for (int i = tid; i < NN * 32; i += 256) {
        const int n  = i >> 5;
        const int cl = i & 31;
        ws[n][cl] = w[n * DD + c0 + cl];
    }

    // Load phase: coalesced LDG.128 along c.
    {
        const int sl = tid >> 3;              // 0..31 (s within tile)
        const int cq = (tid & 7) << 2;        // 0,4,...,28 (c within tile)
        const float4 v = *reinterpret_cast<const float4*>(
            &q[((size_t)b * SS + (s0 + sl)) * DD + c0 + cq]);
        tile[sl][cq + 0] = v.x;
        tile[sl][cq + 1] = v.y;
        tile[sl][cq + 2] = v.z;
        tile[sl][cq + 3] = v.w;
    }
    __syncthreads();

    // Transposed gather: 4 consecutive s-values for one c. Conflict-free
    // (bank = (4*sq + i + cl) mod 32, all distinct within a warp).
    const int cl = tid >> 3;                  // 0..31 (c within tile)
    const int sq = (tid & 7) << 2;            // 0,4,...,28 (s within tile)
    float4 v;
    v.x = tile[sq + 0][cl];
    v.y = tile[sq + 1][cl];
    v.z = tile[sq + 2][cl];
    v.w = tile[sq + 3][cl];

    // Write phase: 20 independent coalesced STG.128 streams (deep store MLP).
    const size_t s_idx = (size_t)(s0 + sq);
    #pragma unroll
    for (int n = 0; n < NN; n++) {
        const float sc = ws[n][cl];
        float4 o;
        o.x = v.x * sc;
        o.y = v.y * sc;
        o.z = v.z * sc;
        o.w = v.w * sc;
        const size_t idx =
            ((size_t)((b * NN + n) * DD + c0 + cl)) * SS + s_idx;
        *reinterpret_cast<float4*>(&out[idx]) = o;
    }
}

extern "C" void kernel_launch(void* const* d_in, const int* in_sizes, int n_in,
                              void* d_out, int out_size)
{
    const float* q = (const float*)d_in[0];   // (8, 2048, 256) fp32
    const float* w = (const float*)d_in[1];   // (20, 256) fp32
    float* out = (float*)d_out;               // (160, 256, 2048) fp32

    dim3 grid(SS / 32, DD / 32, BB);          // (64, 8, 8)
    FeatureReweightingModule_72447508349057_kernel<<<grid, 256>>>(q, w, out);
}

// round 6
// speedup vs baseline: 1.0911x; 1.0911x over previous
#include <cuda_runtime.h>

// out[(b*N+n)*D + c, s] = q[b, s, c] * w[n, c]
// q: (B=8, S=2048, D=256) fp32, c contiguous
// w: (N=20, D=256) fp32
// out: (B*N=160, D=256, S=2048) fp32, s contiguous
//
// Pure HBM-write-bound broadcast-transpose (335.5 MB out, 16.8 MB in).
// R4: 64-wide s-tile, weights preloaded to registers (deep STG MLP),
// streaming stores (__stcs) for the write-once output.

#define BB 8
#define SS 2048
#define DD 256
#define NN 20
#define STILE 64

__global__ __launch_bounds__(256)
void FeatureReweightingModule_72447508349057_kernel(
    const float* __restrict__ q,
    const float* __restrict__ w,
    float* __restrict__ out)
{
    __shared__ float tile[STILE][33];   // [s_local][c_local], padded
    __shared__ float ws[NN][32];        // w slice for this c-tile

    const int s0 = blockIdx.x * STILE;  // 32 s-tiles
    const int c0 = blockIdx.y << 5;     // 8 c-tiles
    const int b  = blockIdx.z;          // 8 batches

    const int tid = threadIdx.x;        // 256 threads

    // Stage the 20x32 weight slice for this channel tile.
    #pragma unroll
    for (int i = tid; i < NN * 32; i += 256) {
        const int n  = i >> 5;
        const int c  = i & 31;
        ws[n][c] = w[n * DD + c0 + c];
    }

    // Load phase: 2 coalesced LDG.128 per thread along c.
    #pragma unroll
    for (int k = 0; k < 2; k++) {
        const int idx = tid + k * 256;
        const int sl  = idx >> 3;             // 0..63
        const int cq  = (idx & 7) << 2;       // 0,4,...,28
        const float4 v = *reinterpret_cast<const float4*>(
            &q[((size_t)b * SS + (s0 + sl)) * DD + c0 + cq]);
        tile[sl][cq + 0] = v.x;
        tile[sl][cq + 1] = v.y;
        tile[sl][cq + 2] = v.z;
        tile[sl][cq + 3] = v.w;
    }
    __syncthreads();

    // Transposed gather: two float4s of consecutive s for one c.
    // Banks (sq+i+cl) mod 32: all 32 distinct per warp -> conflict-free.
    const int cl = tid >> 3;                  // 0..31 (c within tile)
    const int sq = (tid & 7) << 2;            // 0,4,...,28 (s within half-tile)
    float4 v0, v1;
    v0.x = tile[sq + 0][cl];
    v0.y = tile[sq + 1][cl];
    v0.z = tile[sq + 2][cl];
    v0.w = tile[sq + 3][cl];
    v1.x = tile[sq + 32][cl];
    v1.y = tile[sq + 33][cl];
    v1.z = tile[sq + 34][cl];
    v1.w = tile[sq + 35][cl];

    // Preload all 20 weights into registers: store loop becomes pure
    // FMUL + STG with no LDS in the dependency chain.
    float wreg[NN];
    #pragma unroll
    for (int n = 0; n < NN; n++) wreg[n] = ws[n][cl];

    // Write phase: 40 independent streaming STG.128 (deep store MLP).
    float* orow = out + ((size_t)(b * NN) * DD + c0 + cl) * SS + (s0 + sq);
    #pragma unroll
    for (int n = 0; n < NN; n++) {
        const float sc = wreg[n];
        float4 o0, o1;
        o0.x = v0.x * sc; o0.y = v0.y * sc; o0.z = v0.z * sc; o0.w = v0.w * sc;
        o1.x = v1.x * sc; o1.y = v1.y * sc; o1.z = v1.z * sc; o1.w = v1.w * sc;
        float* p = orow + (size_t)n * DD * SS;
        __stcs(reinterpret_cast<float4*>(p), o0);
        __stcs(reinterpret_cast<float4*>(p + 32), o1);
    }
}

extern "C" void kernel_launch(void* const* d_in, const int* in_sizes, int n_in,
                              void* d_out, int out_size)
{
    const float* q = (const float*)d_in[0];   // (8, 2048, 256) fp32
    const float* w = (const float*)d_in[1];   // (20, 256) fp32
    float* out = (float*)d_out;               // (160, 256, 2048) fp32

    dim3 grid(SS / STILE, DD / 32, BB);       // (32, 8, 8) = 2048 blocks
    FeatureReweightingModule_72447508349057_kernel<<<grid, 256>>>(q, w, out);
}